// round 6
// baseline (speedup 1.0000x reference)
#include <cuda_runtime.h>
#include <cuda_bf16.h>
#include <math.h>
#include <stdint.h>

// ---------------- problem constants ----------------
#define TT   8192              // tokens (B*S)
#define DD   2048              // model dim
#define HH   1368              // hidden dim
#define HP   1408              // hidden padded to 64
#define EE   8                 // experts
#define TK   16384             // T * K routed assignments
#define TKS  24576             // TK + TT (shared expert appended as segment 8)
#define WMAT (HH * DD)         // elements per weight matrix

// ---------------- static device scratch ----------------
__device__ __align__(16) float g_y[(size_t)TKS * DD];
__device__ __align__(16) __nv_bfloat16 g_xhi[(size_t)TKS * DD];
__device__ __align__(16) __nv_bfloat16 g_xlo[(size_t)TKS * DD];
__device__ __align__(16) __nv_bfloat16 g_hhi[(size_t)TKS * HP];
__device__ __align__(16) __nv_bfloat16 g_hlo[(size_t)TKS * HP];
__device__ __align__(16) __nv_bfloat16 g_w1h[(size_t)9 * WMAT];
__device__ __align__(16) __nv_bfloat16 g_w1l[(size_t)9 * WMAT];
__device__ __align__(16) __nv_bfloat16 g_w3h[(size_t)9 * WMAT];
__device__ __align__(16) __nv_bfloat16 g_w3l[(size_t)9 * WMAT];
__device__ __align__(16) __nv_bfloat16 g_w2h[(size_t)9 * WMAT];
__device__ __align__(16) __nv_bfloat16 g_w2l[(size_t)9 * WMAT];
__device__ int    g_tok[TKS];
__device__ float  g_gatev[TKS];
__device__ int    g_pos[2 * TT];
__device__ int2   g_top_e[TT];
__device__ float2 g_top_p[TT];
__device__ int    g_cnt1[EE];
__device__ int    g_cntA[EE];
__device__ int    g_cur[EE];
__device__ int    g_seg[10];
__device__ float  g_psum[EE];

// ---------------- PTX helpers (baseline-arch safe) ----------------
__device__ __forceinline__ unsigned smem_u32(const void* p) {
    unsigned a;
    asm("{ .reg .u64 t; cvta.to.shared.u64 t, %1; cvt.u32.u64 %0, t; }"
        : "=r"(a) : "l"(p));
    return a;
}
#define CP_COMMIT()  asm volatile("cp.async.commit_group;" ::: "memory")
#define CP_WAIT0()   asm volatile("cp.async.wait_group 0;" ::: "memory")
#define CP_WAIT1()   asm volatile("cp.async.wait_group 1;" ::: "memory")
#define CP16(dst, src, sz) \
    asm volatile("cp.async.cg.shared.global [%0], [%1], 16, %2;" \
                 :: "r"(dst), "l"(src), "r"(sz))

#define LDSM4(r, addr) \
    asm volatile("ldmatrix.sync.aligned.m8n8.x4.shared.b16 {%0,%1,%2,%3}, [%4];" \
        : "=r"((r)[0]), "=r"((r)[1]), "=r"((r)[2]), "=r"((r)[3]) : "r"(addr))

#define MMA16816(c, a, b0, b1) \
    asm volatile("mma.sync.aligned.m16n8k16.row.col.f32.bf16.bf16.f32 " \
        "{%0,%1,%2,%3}, {%4,%5,%6,%7}, {%8,%9}, {%0,%1,%2,%3};" \
        : "+f"((c)[0]), "+f"((c)[1]), "+f"((c)[2]), "+f"((c)[3]) \
        : "r"((a)[0]), "r"((a)[1]), "r"((a)[2]), "r"((a)[3]), "r"(b0), "r"(b1))

__device__ __forceinline__ void fsplit(float v, __nv_bfloat16& h, __nv_bfloat16& l) {
    h = __float2bfloat16_rn(v);
    l = __float2bfloat16_rn(v - __bfloat162float(h));
}

// ---------------- routing ----------------
__global__ void init_kernel() {
    int i = threadIdx.x;
    if (i < EE) { g_cnt1[i] = 0; g_cntA[i] = 0; g_psum[i] = 0.f; g_cur[i] = 0; }
}

__global__ void router_kernel(const float* __restrict__ x,
                              const float* __restrict__ rw) {
    __shared__ float s_psum[EE];
    __shared__ int s_cnt1[EE], s_cntA[EE];
    int tid = threadIdx.x;
    if (tid < EE) { s_psum[tid] = 0.f; s_cnt1[tid] = 0; s_cntA[tid] = 0; }
    __syncthreads();

    int warp = tid >> 5, lane = tid & 31;
    int t = blockIdx.x * 8 + warp;

    float acc[EE];
#pragma unroll
    for (int e = 0; e < EE; e++) acc[e] = 0.f;
    const float4* xr = reinterpret_cast<const float4*>(x + (long long)t * DD);
    for (int d4 = lane; d4 < DD / 4; d4 += 32) {
        float4 xv = xr[d4];
#pragma unroll
        for (int e = 0; e < EE; e++) {
            float4 wv = reinterpret_cast<const float4*>(rw + (long long)e * DD)[d4];
            acc[e] += xv.x * wv.x + xv.y * wv.y + xv.z * wv.z + xv.w * wv.w;
        }
    }
#pragma unroll
    for (int e = 0; e < EE; e++)
        for (int o = 16; o; o >>= 1)
            acc[e] += __shfl_xor_sync(0xffffffffu, acc[e], o);

    if (lane == 0) {
        float mx = acc[0];
#pragma unroll
        for (int e = 1; e < EE; e++) mx = fmaxf(mx, acc[e]);
        float p[EE], s = 0.f;
#pragma unroll
        for (int e = 0; e < EE; e++) { p[e] = expf(acc[e] - mx); s += p[e]; }
        float inv = 1.f / s;
        int e0 = 0;
#pragma unroll
        for (int e = 1; e < EE; e++) if (acc[e] > acc[e0]) e0 = e;
        int e1 = (e0 == 0) ? 1 : 0;
#pragma unroll
        for (int e = 0; e < EE; e++) if (e != e0 && acc[e] > acc[e1]) e1 = e;

        g_top_e[t] = make_int2(e0, e1);
        g_top_p[t] = make_float2(p[e0] * inv, p[e1] * inv);
        atomicAdd(&s_cnt1[e0], 1);
        atomicAdd(&s_cntA[e0], 1);
        atomicAdd(&s_cntA[e1], 1);
#pragma unroll
        for (int e = 0; e < EE; e++) atomicAdd(&s_psum[e], p[e] * inv);
    }
    __syncthreads();
    if (tid < EE) {
        atomicAdd(&g_psum[tid], s_psum[tid]);
        atomicAdd(&g_cnt1[tid], s_cnt1[tid]);
        atomicAdd(&g_cntA[tid], s_cntA[tid]);
    }
}

__global__ void scan_kernel(float* __restrict__ aux_out) {
    if (threadIdx.x == 0) {
        int off = 0;
        for (int e = 0; e < EE; e++) { g_seg[e] = off; off += g_cntA[e]; }
        g_seg[8] = TK;
        g_seg[9] = TKS;
        float aux = 0.f;
        const float invT = 1.0f / (float)TT;
        for (int e = 0; e < EE; e++)
            aux += ((float)g_cnt1[e] * invT) * (g_psum[e] * invT);
        aux_out[0] = 0.01f * (float)EE * aux;
    }
}

__global__ void build_kernel() {
    int t = blockIdx.x * blockDim.x + threadIdx.x;
    if (t >= TT) return;
    int2 e = g_top_e[t];
    float2 p = g_top_p[t];
    int pos0 = g_seg[e.x] + atomicAdd(&g_cur[e.x], 1);
    g_tok[pos0] = t; g_gatev[pos0] = p.x; g_pos[2 * t] = pos0;
    int pos1 = g_seg[e.y] + atomicAdd(&g_cur[e.y], 1);
    g_tok[pos1] = t; g_gatev[pos1] = p.y; g_pos[2 * t + 1] = pos1;
    g_tok[TK + t] = t; g_gatev[TK + t] = 1.0f;
}

// ---------------- gather + split x ----------------
__global__ void gather_split_x(const float* __restrict__ x) {
    int i = blockIdx.x * blockDim.x + threadIdx.x;
    if (i >= TKS * (DD / 4)) return;
    int s = i >> 9;
    int c = i & 511;
    int tok = g_tok[s];
    float4 v = reinterpret_cast<const float4*>(x)[(long long)tok * (DD / 4) + c];
    __nv_bfloat16 hx, lx, hy, ly, hz, lz, hw, lw;
    fsplit(v.x, hx, lx); fsplit(v.y, hy, ly);
    fsplit(v.z, hz, lz); fsplit(v.w, hw, lw);
    long long o = (long long)s * (DD / 2) + c * 2;
    reinterpret_cast<__nv_bfloat162*>(g_xhi)[o]     = __halves2bfloat162(hx, hy);
    reinterpret_cast<__nv_bfloat162*>(g_xhi)[o + 1] = __halves2bfloat162(hz, hw);
    reinterpret_cast<__nv_bfloat162*>(g_xlo)[o]     = __halves2bfloat162(lx, ly);
    reinterpret_cast<__nv_bfloat162*>(g_xlo)[o + 1] = __halves2bfloat162(lz, lw);
}

// ---------------- weight split ----------------
__global__ void split_w(const float* __restrict__ src,
                        __nv_bfloat16* __restrict__ hi,
                        __nv_bfloat16* __restrict__ lo, int n4) {
    int i = blockIdx.x * blockDim.x + threadIdx.x;
    if (i >= n4) return;
    float4 v = reinterpret_cast<const float4*>(src)[i];
    __nv_bfloat16 hx, lx, hy, ly, hz, lz, hw, lw;
    fsplit(v.x, hx, lx); fsplit(v.y, hy, ly);
    fsplit(v.z, hz, lz); fsplit(v.w, hw, lw);
    long long o = (long long)i * 2;
    reinterpret_cast<__nv_bfloat162*>(hi)[o]     = __halves2bfloat162(hx, hy);
    reinterpret_cast<__nv_bfloat162*>(hi)[o + 1] = __halves2bfloat162(hz, hw);
    reinterpret_cast<__nv_bfloat162*>(lo)[o]     = __halves2bfloat162(lx, ly);
    reinterpret_cast<__nv_bfloat162*>(lo)[o + 1] = __halves2bfloat162(lz, lw);
}

// ============================================================================
// FUSED GEMM1: one CTA computes 128x128 tiles of BOTH x@w1^T and x@w3^T,
// sharing the A smem tiles, then applies SwiGLU + bf16-split in the epilogue
// and writes g_hhi / g_hlo directly. Split-bf16 3-term products, fp32 accum.
// ============================================================================
#define MPITCH 80                           // bytes per smem row (conflict-stagger)
#define MTILE  (128 * MPITCH)               // 10240 bytes per operand tile
#define F1STAGE (6 * MTILE)                 // Ah,Al,B1h,B1l,B3h,B3l
#define F1SMEM  (2 * F1STAGE)               // 122880 bytes
#define MSTAGE (4 * MTILE)                  // gemm2 stage: Ah,Al,Bh,Bl
#define GSMEM  (2 * MSTAGE)                 // 81920 bytes

__device__ __forceinline__ void ld_tiles6(
    unsigned tb, int tid,
    const __nv_bfloat16* __restrict__ Ah, const __nv_bfloat16* __restrict__ Al,
    const __nv_bfloat16* __restrict__ B1h, const __nv_bfloat16* __restrict__ B1l,
    const __nv_bfloat16* __restrict__ B3h, const __nv_bfloat16* __restrict__ B3l,
    int row0, int col0, int kc0)
{
#pragma unroll
    for (int j = 0; j < 2; j++) {
        int idx = j * 256 + tid;         // 0..511
        int r = idx >> 2, c = idx & 3;   // tile row, 16B k-chunk
        unsigned off = (unsigned)(r * MPITCH + c * 16);
        int ar = row0 + r; if (ar >= TKS) ar = TKS - 1;
        long long ga = (long long)ar * DD + kc0 + c * 8;
        CP16(tb + off,             Ah + ga, 16);
        CP16(tb + MTILE + off,     Al + ga, 16);
        int n = col0 + r;
        int ok = (n < HH) ? 16 : 0;
        long long gb = ok ? ((long long)n * DD + kc0 + c * 8) : 0;
        CP16(tb + 2 * MTILE + off, B1h + gb, ok);
        CP16(tb + 3 * MTILE + off, B1l + gb, ok);
        CP16(tb + 4 * MTILE + off, B3h + gb, ok);
        CP16(tb + 5 * MTILE + off, B3l + gb, ok);
    }
    CP_COMMIT();
}

__global__ __launch_bounds__(256)
void gemm1_fused(const __nv_bfloat16* __restrict__ Ah,
                 const __nv_bfloat16* __restrict__ Al,
                 const __nv_bfloat16* __restrict__ W1h,
                 const __nv_bfloat16* __restrict__ W1l,
                 const __nv_bfloat16* __restrict__ W3h,
                 const __nv_bfloat16* __restrict__ W3l,
                 __nv_bfloat16* __restrict__ Hh,
                 __nv_bfloat16* __restrict__ Hl)
{
    extern __shared__ __align__(128) char smem[];
    int z  = blockIdx.z;
    int m0 = g_seg[z], m1 = g_seg[z + 1];
    int row0 = m0 + blockIdx.y * 128;
    if (row0 >= m1) return;
    int col0 = blockIdx.x * 128;

    const __nv_bfloat16* B1h = W1h + (long long)z * WMAT;
    const __nv_bfloat16* B1l = W1l + (long long)z * WMAT;
    const __nv_bfloat16* B3h = W3h + (long long)z * WMAT;
    const __nv_bfloat16* B3l = W3l + (long long)z * WMAT;

    unsigned sb = smem_u32(smem);
    int tid = threadIdx.x, wid = tid >> 5, lane = tid & 31;
    const int nch = DD / 32;                  // 64
    int wm = wid & 3, wn = wid >> 2;

    float acc1[2][8][4], acc3[2][8][4];
#pragma unroll
    for (int t = 0; t < 2; t++)
#pragma unroll
        for (int n = 0; n < 8; n++)
#pragma unroll
            for (int q = 0; q < 4; q++) { acc1[t][n][q] = 0.f; acc3[t][n][q] = 0.f; }

    unsigned a_off[2], b_off[4];
#pragma unroll
    for (int t = 0; t < 2; t++) {
        int rr = wm * 32 + t * 16 + ((lane >> 3) & 1) * 8 + (lane & 7);
        a_off[t] = (unsigned)(rr * MPITCH + (lane >> 4) * 16);
    }
#pragma unroll
    for (int p = 0; p < 4; p++) {
        int nn = wn * 64 + p * 16 + (lane >> 4) * 8 + (lane & 7);
        b_off[p] = (unsigned)(nn * MPITCH + ((lane >> 3) & 1) * 16);
    }

    ld_tiles6(sb, tid, Ah, Al, B1h, B1l, B3h, B3l, row0, col0, 0);

    for (int i = 0; i < nch; i++) {
        if (i + 1 < nch) {
            ld_tiles6(sb + ((i + 1) & 1) * F1STAGE, tid, Ah, Al, B1h, B1l, B3h, B3l,
                      row0, col0, (i + 1) * 32);
            CP_WAIT1();
        } else {
            CP_WAIT0();
        }
        __syncthreads();

        unsigned tb = sb + (i & 1) * F1STAGE;
#pragma unroll
        for (int ks = 0; ks < 2; ks++) {
            unsigned kof = ks * 32;
            unsigned ah[2][4], al[2][4];
            LDSM4(ah[0], tb + a_off[0] + kof);
            LDSM4(ah[1], tb + a_off[1] + kof);
            LDSM4(al[0], tb + MTILE + a_off[0] + kof);
            LDSM4(al[1], tb + MTILE + a_off[1] + kof);
#pragma unroll
            for (int p = 0; p < 4; p++) {
                unsigned b1h[4], b1l[4], b3h[4], b3l[4];
                LDSM4(b1h, tb + 2 * MTILE + b_off[p] + kof);
                LDSM4(b1l, tb + 3 * MTILE + b_off[p] + kof);
                LDSM4(b3h, tb + 4 * MTILE + b_off[p] + kof);
                LDSM4(b3l, tb + 5 * MTILE + b_off[p] + kof);
#pragma unroll
                for (int t = 0; t < 2; t++) {
                    MMA16816(acc1[t][2 * p],     ah[t], b1h[0], b1h[1]);
                    MMA16816(acc1[t][2 * p + 1], ah[t], b1h[2], b1h[3]);
                    MMA16816(acc3[t][2 * p],     ah[t], b3h[0], b3h[1]);
                    MMA16816(acc3[t][2 * p + 1], ah[t], b3h[2], b3h[3]);
                    MMA16816(acc1[t][2 * p],     ah[t], b1l[0], b1l[1]);
                    MMA16816(acc1[t][2 * p + 1], ah[t], b1l[2], b1l[3]);
                    MMA16816(acc3[t][2 * p],     ah[t], b3l[0], b3l[1]);
                    MMA16816(acc3[t][2 * p + 1], ah[t], b3l[2], b3l[3]);
                    MMA16816(acc1[t][2 * p],     al[t], b1h[0], b1h[1]);
                    MMA16816(acc1[t][2 * p + 1], al[t], b1h[2], b1h[3]);
                    MMA16816(acc3[t][2 * p],     al[t], b3h[0], b3h[1]);
                    MMA16816(acc3[t][2 * p + 1], al[t], b3h[2], b3h[3]);
                }
            }
        }
        __syncthreads();
    }

    // fused SwiGLU epilogue: h = silu(acc1) * acc3, split to bf16 hi/lo
#pragma unroll
    for (int t = 0; t < 2; t++) {
        int r0 = row0 + wm * 32 + t * 16 + (lane >> 2);
        int r1 = r0 + 8;
        bool a0 = (r0 < m1), a1 = (r1 < m1);
#pragma unroll
        for (int n = 0; n < 8; n++) {
            int cb = col0 + wn * 64 + n * 8 + 2 * (lane & 3);
            if (a0) {
                float v0 = acc1[t][n][0], v1 = acc1[t][n][1];
                float h0 = v0 / (1.f + __expf(-v0)) * acc3[t][n][0];
                float h1 = v1 / (1.f + __expf(-v1)) * acc3[t][n][1];
                __nv_bfloat16 h0h, h0l, h1h, h1l;
                fsplit(h0, h0h, h0l); fsplit(h1, h1h, h1l);
                long long o = (long long)r0 * HP + cb;
                *reinterpret_cast<__nv_bfloat162*>(Hh + o) = __halves2bfloat162(h0h, h1h);
                *reinterpret_cast<__nv_bfloat162*>(Hl + o) = __halves2bfloat162(h0l, h1l);
            }
            if (a1) {
                float v0 = acc1[t][n][2], v1 = acc1[t][n][3];
                float h0 = v0 / (1.f + __expf(-v0)) * acc3[t][n][2];
                float h1 = v1 / (1.f + __expf(-v1)) * acc3[t][n][3];
                __nv_bfloat16 h0h, h0l, h1h, h1l;
                fsplit(h0, h0h, h0l); fsplit(h1, h1h, h1l);
                long long o = (long long)r1 * HP + cb;
                *reinterpret_cast<__nv_bfloat162*>(Hh + o) = __halves2bfloat162(h0h, h1h);
                *reinterpret_cast<__nv_bfloat162*>(Hl + o) = __halves2bfloat162(h0l, h1l);
            }
        }
    }
}

// ============================================================================
// GEMM2 (grouped split-bf16, gated fp32 output) — same structure as before
// ============================================================================
__device__ __forceinline__ void ld_tiles4(
    unsigned tb, int tid,
    const __nv_bfloat16* __restrict__ Ah, const __nv_bfloat16* __restrict__ Al,
    const __nv_bfloat16* __restrict__ Bh, const __nv_bfloat16* __restrict__ Bl,
    int row0, int lda, int col0, int nreal, int kreal, int kc0)
{
#pragma unroll
    for (int j = 0; j < 2; j++) {
        int idx = j * 256 + tid;
        int r = idx >> 2, c = idx & 3;
        unsigned off = (unsigned)(r * MPITCH + c * 16);
        int ar = row0 + r; if (ar >= TKS) ar = TKS - 1;
        long long ga = (long long)ar * lda + kc0 + c * 8;
        CP16(tb + off,             Ah + ga, 16);
        CP16(tb + MTILE + off,     Al + ga, 16);
        int n = col0 + r, kg = kc0 + c * 8;
        int ok = (n < nreal && kg < kreal) ? 16 : 0;
        long long gb = ok ? ((long long)n * kreal + kg) : 0;
        CP16(tb + 2 * MTILE + off, Bh + gb, ok);
        CP16(tb + 3 * MTILE + off, Bl + gb, ok);
    }
    CP_COMMIT();
}

__global__ __launch_bounds__(256)
void gemm_sp(const __nv_bfloat16* __restrict__ Ah,
             const __nv_bfloat16* __restrict__ Al,
             const __nv_bfloat16* __restrict__ Wh,
             const __nv_bfloat16* __restrict__ Wl,
             float* __restrict__ C,
             const float* __restrict__ gate,
             int lda, int ldc, int nreal, int kreal, int kpad)
{
    extern __shared__ __align__(128) char smem[];
    int z  = blockIdx.z;
    int m0 = g_seg[z], m1 = g_seg[z + 1];
    int row0 = m0 + blockIdx.y * 128;
    if (row0 >= m1) return;
    int col0 = blockIdx.x * 128;

    const __nv_bfloat16* Bh = Wh + (long long)z * WMAT;
    const __nv_bfloat16* Bl = Wl + (long long)z * WMAT;

    unsigned sb = smem_u32(smem);
    int tid = threadIdx.x, wid = tid >> 5, lane = tid & 31;
    int nch = kpad / 32;
    int wm = wid & 3, wn = wid >> 2;

    float acc[2][8][4];
#pragma unroll
    for (int t = 0; t < 2; t++)
#pragma unroll
        for (int n = 0; n < 8; n++)
#pragma unroll
            for (int q = 0; q < 4; q++) acc[t][n][q] = 0.f;

    unsigned a_off[2], b_off[4];
#pragma unroll
    for (int t = 0; t < 2; t++) {
        int rr = wm * 32 + t * 16 + ((lane >> 3) & 1) * 8 + (lane & 7);
        a_off[t] = (unsigned)(rr * MPITCH + (lane >> 4) * 16);
    }
#pragma unroll
    for (int p = 0; p < 4; p++) {
        int nn = wn * 64 + p * 16 + (lane >> 4) * 8 + (lane & 7);
        b_off[p] = (unsigned)(nn * MPITCH + ((lane >> 3) & 1) * 16);
    }

    ld_tiles4(sb, tid, Ah, Al, Bh, Bl, row0, lda, col0, nreal, kreal, 0);

    for (int i = 0; i < nch; i++) {
        if (i + 1 < nch) {
            ld_tiles4(sb + ((i + 1) & 1) * MSTAGE, tid, Ah, Al, Bh, Bl,
                      row0, lda, col0, nreal, kreal, (i + 1) * 32);
            CP_WAIT1();
        } else {
            CP_WAIT0();
        }
        __syncthreads();

        unsigned tb = sb + (i & 1) * MSTAGE;
#pragma unroll
        for (int ks = 0; ks < 2; ks++) {
            unsigned kof = ks * 32;
            unsigned ah[2][4], al[2][4], bhv[4][4], blv[4][4];
            LDSM4(ah[0], tb + a_off[0] + kof);
            LDSM4(ah[1], tb + a_off[1] + kof);
            LDSM4(al[0], tb + MTILE + a_off[0] + kof);
            LDSM4(al[1], tb + MTILE + a_off[1] + kof);
#pragma unroll
            for (int p = 0; p < 4; p++) {
                LDSM4(bhv[p], tb + 2 * MTILE + b_off[p] + kof);
                LDSM4(blv[p], tb + 3 * MTILE + b_off[p] + kof);
            }
#pragma unroll
            for (int p = 0; p < 4; p++)
#pragma unroll
                for (int t = 0; t < 2; t++) {
                    MMA16816(acc[t][2 * p],     ah[t], bhv[p][0], bhv[p][1]);
                    MMA16816(acc[t][2 * p + 1], ah[t], bhv[p][2], bhv[p][3]);
                }
#pragma unroll
            for (int p = 0; p < 4; p++)
#pragma unroll
                for (int t = 0; t < 2; t++) {
                    MMA16816(acc[t][2 * p],     ah[t], blv[p][0], blv[p][1]);
                    MMA16816(acc[t][2 * p + 1], ah[t], blv[p][2], blv[p][3]);
                }
#pragma unroll
            for (int p = 0; p < 4; p++)
#pragma unroll
                for (int t = 0; t < 2; t++) {
                    MMA16816(acc[t][2 * p],     al[t], bhv[p][0], bhv[p][1]);
                    MMA16816(acc[t][2 * p + 1], al[t], bhv[p][2], bhv[p][3]);
                }
        }
        __syncthreads();
    }

#pragma unroll
    for (int t = 0; t < 2; t++) {
        int r0 = row0 + wm * 32 + t * 16 + (lane >> 2);
        int r1 = r0 + 8;
        float g0 = 1.f, g1 = 1.f;
        bool a0 = (r0 < m1), a1 = (r1 < m1);
        if (gate != nullptr) {
            if (a0) g0 = gate[r0];
            if (a1) g1 = gate[r1];
        }
#pragma unroll
        for (int n = 0; n < 8; n++) {
            int cb = col0 + wn * 64 + n * 8 + 2 * (lane & 3);
            if (a0) {
                float2 v = make_float2(acc[t][n][0] * g0, acc[t][n][1] * g0);
                *reinterpret_cast<float2*>(C + (long long)r0 * ldc + cb) = v;
            }
            if (a1) {
                float2 v = make_float2(acc[t][n][2] * g1, acc[t][n][3] * g1);
                *reinterpret_cast<float2*>(C + (long long)r1 * ldc + cb) = v;
            }
        }
    }
}

// ---------------- final deterministic 3-slot add ----------------
__global__ void final_add(float* __restrict__ out) {
    int i = blockIdx.x * blockDim.x + threadIdx.x;
    if (i >= TT * (DD / 4)) return;
    int t = i >> 9, c = i & 511;
    int p0 = g_pos[2 * t], p1 = g_pos[2 * t + 1], p2 = TK + t;
    const float4* y4 = reinterpret_cast<const float4*>(g_y);
    float4 a = y4[(long long)p0 * 512 + c];
    float4 b = y4[(long long)p1 * 512 + c];
    float4 d = y4[(long long)p2 * 512 + c];
    float4 v;
    v.x = a.x + b.x + d.x; v.y = a.y + b.y + d.y;
    v.z = a.z + b.z + d.z; v.w = a.w + b.w + d.w;
    reinterpret_cast<float4*>(out)[(long long)t * 512 + c] = v;
}

// ---------------- launch ----------------
extern "C" void kernel_launch(void* const* d_in, const int* in_sizes, int n_in,
                              void* d_out, int out_size) {
    const float* x   = (const float*)d_in[0];
    const float* rw  = (const float*)d_in[1];
    const float* w1  = (const float*)d_in[2];
    const float* w2  = (const float*)d_in[3];
    const float* w3  = (const float*)d_in[4];
    const float* sw1 = (const float*)d_in[5];
    const float* sw2 = (const float*)d_in[6];
    const float* sw3 = (const float*)d_in[7];
    float* out = (float*)d_out;

    float *pY, *pGate;
    __nv_bfloat16 *pXh, *pXl, *pHh, *pHl;
    __nv_bfloat16 *pW1h, *pW1l, *pW3h, *pW3l, *pW2h, *pW2l;
    cudaGetSymbolAddress((void**)&pY,    g_y);
    cudaGetSymbolAddress((void**)&pGate, g_gatev);
    cudaGetSymbolAddress((void**)&pXh,   g_xhi);
    cudaGetSymbolAddress((void**)&pXl,   g_xlo);
    cudaGetSymbolAddress((void**)&pHh,   g_hhi);
    cudaGetSymbolAddress((void**)&pHl,   g_hlo);
    cudaGetSymbolAddress((void**)&pW1h,  g_w1h);
    cudaGetSymbolAddress((void**)&pW1l,  g_w1l);
    cudaGetSymbolAddress((void**)&pW3h,  g_w3h);
    cudaGetSymbolAddress((void**)&pW3l,  g_w3l);
    cudaGetSymbolAddress((void**)&pW2h,  g_w2h);
    cudaGetSymbolAddress((void**)&pW2l,  g_w2l);

    cudaFuncSetAttribute(gemm1_fused, cudaFuncAttributeMaxDynamicSharedMemorySize, F1SMEM);
    cudaFuncSetAttribute(gemm_sp,     cudaFuncAttributeMaxDynamicSharedMemorySize, GSMEM);

    // routing
    init_kernel<<<1, 32>>>();
    router_kernel<<<TT / 8, 256>>>(x, rw);
    scan_kernel<<<1, 32>>>(out + (long long)TT * DD);
    build_kernel<<<TT / 256, 256>>>();

    // gather + splits
    gather_split_x<<<(TKS * (DD / 4) + 255) / 256, 256>>>(x);
    int nw = 8 * WMAT / 4, ns = WMAT / 4;
    split_w<<<(nw + 255) / 256, 256>>>(w1,  pW1h,            pW1l,            nw);
    split_w<<<(ns + 255) / 256, 256>>>(sw1, pW1h + (size_t)8 * WMAT, pW1l + (size_t)8 * WMAT, ns);
    split_w<<<(nw + 255) / 256, 256>>>(w3,  pW3h,            pW3l,            nw);
    split_w<<<(ns + 255) / 256, 256>>>(sw3, pW3h + (size_t)8 * WMAT, pW3l + (size_t)8 * WMAT, ns);
    split_w<<<(nw + 255) / 256, 256>>>(w2,  pW2h,            pW2l,            nw);
    split_w<<<(ns + 255) / 256, 256>>>(sw2, pW2h + (size_t)8 * WMAT, pW2l + (size_t)8 * WMAT, ns);

    // fused GEMM1 + SwiGLU: writes g_hhi / g_hlo directly
    dim3 grid1(11, 128, 9);
    gemm1_fused<<<grid1, 256, F1SMEM>>>(pXh, pXl, pW1h, pW1l, pW3h, pW3l, pHh, pHl);

    // GEMM2: [TKS, HP] @ [DD, HH]^T -> y (gated); K iterates 1376 (>= HH, zero pad)
    dim3 grid2(16, 128, 9);
    gemm_sp<<<grid2, 256, GSMEM>>>(pHh, pHl, pW2h, pW2l, pY, pGate,
                                   HP, DD, DD, HH, 1376);

    final_add<<<(TT * (DD / 4)) / 256, 256>>>(out);
}

// round 8
// speedup vs baseline: 1.4826x; 1.4826x over previous
#include <cuda_runtime.h>
#include <cuda_bf16.h>
#include <math.h>
#include <stdint.h>

// ---------------- problem constants ----------------
#define TT   8192              // tokens (B*S)
#define DD   2048              // model dim
#define HH   1368              // hidden dim
#define HP   1408              // hidden padded to 64
#define EE   8                 // experts
#define TK   16384             // T * K routed assignments
#define TKS  24576             // TK + TT (shared expert appended as segment 8)
#define WMAT (HH * DD)         // elements per weight matrix

// ---------------- static device scratch (all fp32, tf32-rounded) ----------
__device__ __align__(16) float g_xr[(size_t)TKS * DD];     // gathered + rounded x
__device__ __align__(16) float g_h[(size_t)TKS * HP];      // swiglu output (rounded)
__device__ __align__(16) float g_bufA[(size_t)TKS * HP];   // x@w1^T
__device__ __align__(16) float g_bufB[(size_t)TKS * HP];   // x@w3^T
__device__ __align__(16) float g_y[(size_t)TKS * DD];      // gemm2 output slots
__device__ __align__(16) float g_w1r[(size_t)9 * WMAT];
__device__ __align__(16) float g_w3r[(size_t)9 * WMAT];
__device__ __align__(16) float g_w2r[(size_t)9 * WMAT];
__device__ int    g_tok[TKS];
__device__ float  g_gatev[TKS];
__device__ int    g_pos[2 * TT];
__device__ int2   g_top_e[TT];
__device__ float2 g_top_p[TT];
__device__ int    g_cnt1[EE];
__device__ int    g_cntA[EE];
__device__ int    g_cur[EE];
__device__ int    g_seg[10];
__device__ float  g_psum[EE];

// ---------------- PTX helpers (baseline-arch safe) ----------------
__device__ __forceinline__ unsigned smem_u32(const void* p) {
    unsigned a;
    asm("{ .reg .u64 t; cvta.to.shared.u64 t, %1; cvt.u32.u64 %0, t; }"
        : "=r"(a) : "l"(p));
    return a;
}
#define CP_COMMIT()  asm volatile("cp.async.commit_group;" ::: "memory")
#define CP_WAIT0()   asm volatile("cp.async.wait_group 0;" ::: "memory")
#define CP_WAIT1()   asm volatile("cp.async.wait_group 1;" ::: "memory")
#define CP16(dst, src, sz) \
    asm volatile("cp.async.cg.shared.global [%0], [%1], 16, %2;" \
                 :: "r"(dst), "l"(src), "r"(sz))

#define LDSM4(r, addr) \
    asm volatile("ldmatrix.sync.aligned.m8n8.x4.shared.b16 {%0,%1,%2,%3}, [%4];" \
        : "=r"((r)[0]), "=r"((r)[1]), "=r"((r)[2]), "=r"((r)[3]) : "r"(addr))

#define MMATF32(c, a, b0, b1) \
    asm volatile("mma.sync.aligned.m16n8k8.row.col.f32.tf32.tf32.f32 " \
        "{%0,%1,%2,%3}, {%4,%5,%6,%7}, {%8,%9}, {%0,%1,%2,%3};" \
        : "+f"((c)[0]), "+f"((c)[1]), "+f"((c)[2]), "+f"((c)[3]) \
        : "r"((a)[0]), "r"((a)[1]), "r"((a)[2]), "r"((a)[3]), "r"(b0), "r"(b1))

__device__ __forceinline__ float tf32r(float v) {
    unsigned r;
    asm("cvt.rna.tf32.f32 %0, %1;" : "=r"(r) : "f"(v));
    return __uint_as_float(r);
}

// ---------------- routing ----------------
__global__ void init_kernel() {
    int i = threadIdx.x;
    if (i < EE) { g_cnt1[i] = 0; g_cntA[i] = 0; g_psum[i] = 0.f; g_cur[i] = 0; }
}

__global__ void router_kernel(const float* __restrict__ x,
                              const float* __restrict__ rw) {
    __shared__ float s_psum[EE];
    __shared__ int s_cnt1[EE], s_cntA[EE];
    int tid = threadIdx.x;
    if (tid < EE) { s_psum[tid] = 0.f; s_cnt1[tid] = 0; s_cntA[tid] = 0; }
    __syncthreads();

    int warp = tid >> 5, lane = tid & 31;
    int t = blockIdx.x * 8 + warp;

    float acc[EE];
#pragma unroll
    for (int e = 0; e < EE; e++) acc[e] = 0.f;
    const float4* xr = reinterpret_cast<const float4*>(x + (long long)t * DD);
    for (int d4 = lane; d4 < DD / 4; d4 += 32) {
        float4 xv = xr[d4];
#pragma unroll
        for (int e = 0; e < EE; e++) {
            float4 wv = reinterpret_cast<const float4*>(rw + (long long)e * DD)[d4];
            acc[e] += xv.x * wv.x + xv.y * wv.y + xv.z * wv.z + xv.w * wv.w;
        }
    }
#pragma unroll
    for (int e = 0; e < EE; e++)
        for (int o = 16; o; o >>= 1)
            acc[e] += __shfl_xor_sync(0xffffffffu, acc[e], o);

    if (lane == 0) {
        float mx = acc[0];
#pragma unroll
        for (int e = 1; e < EE; e++) mx = fmaxf(mx, acc[e]);
        float p[EE], s = 0.f;
#pragma unroll
        for (int e = 0; e < EE; e++) { p[e] = expf(acc[e] - mx); s += p[e]; }
        float inv = 1.f / s;
        int e0 = 0;
#pragma unroll
        for (int e = 1; e < EE; e++) if (acc[e] > acc[e0]) e0 = e;
        int e1 = (e0 == 0) ? 1 : 0;
#pragma unroll
        for (int e = 0; e < EE; e++) if (e != e0 && acc[e] > acc[e1]) e1 = e;

        g_top_e[t] = make_int2(e0, e1);
        g_top_p[t] = make_float2(p[e0] * inv, p[e1] * inv);
        atomicAdd(&s_cnt1[e0], 1);
        atomicAdd(&s_cntA[e0], 1);
        atomicAdd(&s_cntA[e1], 1);
#pragma unroll
        for (int e = 0; e < EE; e++) atomicAdd(&s_psum[e], p[e] * inv);
    }
    __syncthreads();
    if (tid < EE) {
        atomicAdd(&g_psum[tid], s_psum[tid]);
        atomicAdd(&g_cnt1[tid], s_cnt1[tid]);
        atomicAdd(&g_cntA[tid], s_cntA[tid]);
    }
}

__global__ void scan_kernel(float* __restrict__ aux_out) {
    if (threadIdx.x == 0) {
        int off = 0;
        for (int e = 0; e < EE; e++) { g_seg[e] = off; off += g_cntA[e]; }
        g_seg[8] = TK;
        g_seg[9] = TKS;
        float aux = 0.f;
        const float invT = 1.0f / (float)TT;
        for (int e = 0; e < EE; e++)
            aux += ((float)g_cnt1[e] * invT) * (g_psum[e] * invT);
        aux_out[0] = 0.01f * (float)EE * aux;
    }
}

__global__ void build_kernel() {
    int t = blockIdx.x * blockDim.x + threadIdx.x;
    if (t >= TT) return;
    int2 e = g_top_e[t];
    float2 p = g_top_p[t];
    int pos0 = g_seg[e.x] + atomicAdd(&g_cur[e.x], 1);
    g_tok[pos0] = t; g_gatev[pos0] = p.x; g_pos[2 * t] = pos0;
    int pos1 = g_seg[e.y] + atomicAdd(&g_cur[e.y], 1);
    g_tok[pos1] = t; g_gatev[pos1] = p.y; g_pos[2 * t + 1] = pos1;
    g_tok[TK + t] = t; g_gatev[TK + t] = 1.0f;
}

// ---------------- gather + tf32-round x ----------------
__global__ void gather_round_x(const float* __restrict__ x) {
    int i = blockIdx.x * blockDim.x + threadIdx.x;
    if (i >= TKS * (DD / 4)) return;
    int s = i >> 9;
    int c = i & 511;
    int tok = g_tok[s];
    float4 v = reinterpret_cast<const float4*>(x)[(long long)tok * (DD / 4) + c];
    v.x = tf32r(v.x); v.y = tf32r(v.y); v.z = tf32r(v.z); v.w = tf32r(v.w);
    reinterpret_cast<float4*>(g_xr)[(long long)s * (DD / 4) + c] = v;
}

// ---------------- tf32-round weights ----------------
__global__ void round_w(const float* __restrict__ src,
                        float* __restrict__ dst, int n4) {
    int i = blockIdx.x * blockDim.x + threadIdx.x;
    if (i >= n4) return;
    float4 v = reinterpret_cast<const float4*>(src)[i];
    v.x = tf32r(v.x); v.y = tf32r(v.y); v.z = tf32r(v.z); v.w = tf32r(v.w);
    reinterpret_cast<float4*>(dst)[i] = v;
}

// ---------------- swiglu (fp32 in, tf32-rounded fp32 out) ----------------
__global__ void swiglu_round(int n4) {
    int i = blockIdx.x * blockDim.x + threadIdx.x;
    if (i >= n4) return;
    float4 a = reinterpret_cast<const float4*>(g_bufA)[i];
    float4 b = reinterpret_cast<const float4*>(g_bufB)[i];
    float4 h;
    h.x = tf32r(a.x / (1.f + __expf(-a.x)) * b.x);
    h.y = tf32r(a.y / (1.f + __expf(-a.y)) * b.y);
    h.z = tf32r(a.z / (1.f + __expf(-a.z)) * b.z);
    h.w = tf32r(a.w / (1.f + __expf(-a.w)) * b.w);
    reinterpret_cast<float4*>(g_h)[i] = h;
}

// ============================================================================
// grouped TF32 GEMM via mma.sync m16n8k8 (single term, fp32 accumulate)
// C[m, col0:col0+128) = sum_k A[m,k] * W[z][n,k]
// 128x128 CTA tile, K32 chunks, 2-stage double buffer, 2 CTAs/SM.
// ============================================================================
#define TPITCH 144                          // bytes per smem row (32 tf32 + pad)
#define TTILE  (128 * TPITCH)               // 18432 bytes per operand tile
#define TSTAGE (2 * TTILE)                  // 36864 (A, B)
#define TSMEM  (2 * TSTAGE)                 // 73728 bytes total

__device__ __forceinline__ void ld_tiles_t(
    unsigned tb, int tid,
    const float* __restrict__ A, const float* __restrict__ B,
    int row0, int lda, int col0, int ldb, int nreal, int kreal, int kc0)
{
#pragma unroll
    for (int j = 0; j < 4; j++) {
        int idx = j * 256 + tid;         // 0..1023
        int r = idx >> 3, c = idx & 7;   // tile row, 16B chunk (4 tf32)
        unsigned off = (unsigned)(r * TPITCH + c * 16);
        int ar = row0 + r; if (ar >= TKS) ar = TKS - 1;
        long long ga = (long long)ar * lda + kc0 + c * 4;
        CP16(tb + off, A + ga, 16);
        int n = col0 + r, kg = kc0 + c * 4;
        int ok = (n < nreal && kg < kreal) ? 16 : 0;
        long long gb = ok ? ((long long)n * ldb + kg) : 0;
        CP16(tb + TTILE + off, B + gb, ok);
    }
    CP_COMMIT();
}

__global__ __launch_bounds__(256, 2)
void gemm_t32(const float* __restrict__ A,
              const float* __restrict__ W,
              float* __restrict__ C,
              const float* __restrict__ gate,
              int lda, int ldb, int ldc, int nreal, int kreal, int kpad)
{
    extern __shared__ __align__(128) char smem[];
    int z  = blockIdx.z;
    int m0 = g_seg[z], m1 = g_seg[z + 1];
    int row0 = m0 + blockIdx.y * 128;
    if (row0 >= m1) return;
    int col0 = blockIdx.x * 128;

    const float* B = W + (long long)z * WMAT;

    unsigned sb = smem_u32(smem);
    int tid = threadIdx.x, wid = tid >> 5, lane = tid & 31;
    int nch = kpad / 32;
    int wm = wid & 3, wn = wid >> 2;          // warp -> (m32 slot, n64 slot)

    float acc[2][8][4];
#pragma unroll
    for (int t = 0; t < 2; t++)
#pragma unroll
        for (int n = 0; n < 8; n++)
#pragma unroll
            for (int q = 0; q < 4; q++) acc[t][n][q] = 0.f;

    // ldmatrix base offsets (k-step byte advance added in loop)
    // A m16 frag at rows R..R+15: addr = (R + lane&15)*pitch + (lane>>4)*16
    unsigned a_off[2];
#pragma unroll
    for (int t = 0; t < 2; t++) {
        int rr = wm * 32 + t * 16 + (lane & 15);
        a_off[t] = (unsigned)(rr * TPITCH + (lane >> 4) * 16);
    }
    // B n16 frag: rows n0 + (lane&7) + ((lane>>4)<<3), byte ((lane>>3)&1)*16
    unsigned b_off[4];
#pragma unroll
    for (int p = 0; p < 4; p++) {
        int nn = wn * 64 + p * 16 + (lane & 7) + ((lane >> 4) << 3);
        b_off[p] = (unsigned)(nn * TPITCH + ((lane >> 3) & 1) * 16);
    }

    ld_tiles_t(sb, tid, A, B, row0, lda, col0, ldb, nreal, kreal, 0);

    for (int i = 0; i < nch; i++) {
        if (i + 1 < nch) {
            ld_tiles_t(sb + ((i + 1) & 1) * TSTAGE, tid, A, B,
                       row0, lda, col0, ldb, nreal, kreal, (i + 1) * 32);
            CP_WAIT1();
        } else {
            CP_WAIT0();
        }
        __syncthreads();

        unsigned tb = sb + (i & 1) * TSTAGE;
#pragma unroll
        for (int ks = 0; ks < 4; ks++) {
            unsigned kof = ks * 32;          // k8 step = 8 tf32 = 32 BYTES
            unsigned av[2][4], bv[4][4];
            LDSM4(av[0], tb + a_off[0] + kof);
            LDSM4(av[1], tb + a_off[1] + kof);
#pragma unroll
            for (int p = 0; p < 4; p++)
                LDSM4(bv[p], tb + TTILE + b_off[p] + kof);
#pragma unroll
            for (int p = 0; p < 4; p++)
#pragma unroll
                for (int t = 0; t < 2; t++) {
                    MMATF32(acc[t][2 * p],     av[t], bv[p][0], bv[p][1]);
                    MMATF32(acc[t][2 * p + 1], av[t], bv[p][2], bv[p][3]);
                }
        }
        __syncthreads();
    }

    // epilogue (same fragment layout as f16 MMA family)
#pragma unroll
    for (int t = 0; t < 2; t++) {
        int r0 = row0 + wm * 32 + t * 16 + (lane >> 2);
        int r1 = r0 + 8;
        float g0 = 1.f, g1 = 1.f;
        bool a0 = (r0 < m1), a1 = (r1 < m1);
        if (gate != nullptr) {
            if (a0) g0 = gate[r0];
            if (a1) g1 = gate[r1];
        }
#pragma unroll
        for (int n = 0; n < 8; n++) {
            int cb = col0 + wn * 64 + n * 8 + 2 * (lane & 3);
            if (a0) {
                float2 v = make_float2(acc[t][n][0] * g0, acc[t][n][1] * g0);
                *reinterpret_cast<float2*>(C + (long long)r0 * ldc + cb) = v;
            }
            if (a1) {
                float2 v = make_float2(acc[t][n][2] * g1, acc[t][n][3] * g1);
                *reinterpret_cast<float2*>(C + (long long)r1 * ldc + cb) = v;
            }
        }
    }
}

// ---------------- final deterministic 3-slot add ----------------
__global__ void final_add(float* __restrict__ out) {
    int i = blockIdx.x * blockDim.x + threadIdx.x;
    if (i >= TT * (DD / 4)) return;
    int t = i >> 9, c = i & 511;
    int p0 = g_pos[2 * t], p1 = g_pos[2 * t + 1], p2 = TK + t;
    const float4* y4 = reinterpret_cast<const float4*>(g_y);
    float4 a = y4[(long long)p0 * 512 + c];
    float4 b = y4[(long long)p1 * 512 + c];
    float4 d = y4[(long long)p2 * 512 + c];
    float4 v;
    v.x = a.x + b.x + d.x; v.y = a.y + b.y + d.y;
    v.z = a.z + b.z + d.z; v.w = a.w + b.w + d.w;
    reinterpret_cast<float4*>(out)[(long long)t * 512 + c] = v;
}

// ---------------- launch ----------------
extern "C" void kernel_launch(void* const* d_in, const int* in_sizes, int n_in,
                              void* d_out, int out_size) {
    const float* x   = (const float*)d_in[0];
    const float* rw  = (const float*)d_in[1];
    const float* w1  = (const float*)d_in[2];
    const float* w2  = (const float*)d_in[3];
    const float* w3  = (const float*)d_in[4];
    const float* sw1 = (const float*)d_in[5];
    const float* sw2 = (const float*)d_in[6];
    const float* sw3 = (const float*)d_in[7];
    float* out = (float*)d_out;

    float *pXr, *pH, *pBufA, *pBufB, *pY, *pGate;
    float *pW1r, *pW3r, *pW2r;
    cudaGetSymbolAddress((void**)&pXr,   g_xr);
    cudaGetSymbolAddress((void**)&pH,    g_h);
    cudaGetSymbolAddress((void**)&pBufA, g_bufA);
    cudaGetSymbolAddress((void**)&pBufB, g_bufB);
    cudaGetSymbolAddress((void**)&pY,    g_y);
    cudaGetSymbolAddress((void**)&pGate, g_gatev);
    cudaGetSymbolAddress((void**)&pW1r,  g_w1r);
    cudaGetSymbolAddress((void**)&pW3r,  g_w3r);
    cudaGetSymbolAddress((void**)&pW2r,  g_w2r);

    cudaFuncSetAttribute(gemm_t32, cudaFuncAttributeMaxDynamicSharedMemorySize, TSMEM);

    // routing
    init_kernel<<<1, 32>>>();
    router_kernel<<<TT / 8, 256>>>(x, rw);
    scan_kernel<<<1, 32>>>(out + (long long)TT * DD);
    build_kernel<<<TT / 256, 256>>>();

    // gather + rounds
    gather_round_x<<<(TKS * (DD / 4) + 255) / 256, 256>>>(x);
    int nw = 8 * WMAT / 4, ns = WMAT / 4;
    round_w<<<(nw + 255) / 256, 256>>>(w1,  pW1r,                    nw);
    round_w<<<(ns + 255) / 256, 256>>>(sw1, pW1r + (size_t)8 * WMAT, ns);
    round_w<<<(nw + 255) / 256, 256>>>(w3,  pW3r,                    nw);
    round_w<<<(ns + 255) / 256, 256>>>(sw3, pW3r + (size_t)8 * WMAT, ns);
    round_w<<<(nw + 255) / 256, 256>>>(w2,  pW2r,                    nw);
    round_w<<<(ns + 255) / 256, 256>>>(sw2, pW2r + (size_t)8 * WMAT, ns);

    // GEMM1: [TKS, DD] @ [HH, DD]^T -> bufA / bufB (ldc = HP)
    dim3 grid1(11, 64, 9);
    gemm_t32<<<grid1, 256, TSMEM>>>(pXr, pW1r, pBufA, nullptr,
                                    DD, DD, HP, HH, DD, DD);
    gemm_t32<<<grid1, 256, TSMEM>>>(pXr, pW3r, pBufB, nullptr,
                                    DD, DD, HP, HH, DD, DD);

    // swiglu + tf32 round
    {
        int n4 = TKS * HP / 4;
        swiglu_round<<<(n4 + 255) / 256, 256>>>(n4);
    }

    // GEMM2: [TKS, HP] @ [DD, HH]^T -> y (gated); K iterates 1376 (>= HH)
    dim3 grid2(16, 64, 9);
    gemm_t32<<<grid2, 256, TSMEM>>>(pH, pW2r, pY, pGate,
                                    HP, HH, DD, DD, HH, 1376);

    final_add<<<(TT * (DD / 4)) / 256, 256>>>(out);
}

// round 9
// speedup vs baseline: 2.3219x; 1.5661x over previous
#include <cuda_runtime.h>
#include <cuda_fp16.h>
#include <math.h>
#include <stdint.h>

// ---------------- problem constants ----------------
#define TT   8192              // tokens (B*S)
#define DD   2048              // model dim
#define HH   1368              // hidden dim
#define HP   1408              // hidden padded to 64
#define EE   8                 // experts
#define TK   16384             // T * K routed assignments
#define TKS  24576             // TK + TT (shared expert appended as segment 8)
#define WMAT (HH * DD)         // elements per weight matrix

// ---------------- static device scratch ----------------
__device__ __align__(16) __half g_xh[(size_t)TKS * DD];    // gathered x (fp16)
__device__ __align__(16) __half g_hh[(size_t)TKS * HP];    // swiglu output (fp16)
__device__ __align__(16) float  g_bufA[(size_t)TKS * HP];  // x@w1^T (fp32)
__device__ __align__(16) float  g_bufB[(size_t)TKS * HP];  // x@w3^T (fp32)
__device__ __align__(16) float  g_y[(size_t)TKS * DD];     // gemm2 output slots
__device__ __align__(16) __half g_w1h[(size_t)9 * WMAT];
__device__ __align__(16) __half g_w3h[(size_t)9 * WMAT];
__device__ __align__(16) __half g_w2h[(size_t)9 * WMAT];
__device__ int    g_tok[TKS];
__device__ float  g_gatev[TKS];
__device__ int    g_pos[2 * TT];
__device__ int2   g_top_e[TT];
__device__ float2 g_top_p[TT];
__device__ int    g_cnt1[EE];
__device__ int    g_cntA[EE];
__device__ int    g_cur[EE];
__device__ int    g_seg[10];
__device__ float  g_psum[EE];

// ---------------- PTX helpers (baseline-arch safe) ----------------
__device__ __forceinline__ unsigned smem_u32(const void* p) {
    unsigned a;
    asm("{ .reg .u64 t; cvta.to.shared.u64 t, %1; cvt.u32.u64 %0, t; }"
        : "=r"(a) : "l"(p));
    return a;
}
#define CP_COMMIT()  asm volatile("cp.async.commit_group;" ::: "memory")
#define CP_WAIT0()   asm volatile("cp.async.wait_group 0;" ::: "memory")
#define CP_WAIT1()   asm volatile("cp.async.wait_group 1;" ::: "memory")
#define CP16(dst, src, sz) \
    asm volatile("cp.async.cg.shared.global [%0], [%1], 16, %2;" \
                 :: "r"(dst), "l"(src), "r"(sz))

#define LDSM4(r, addr) \
    asm volatile("ldmatrix.sync.aligned.m8n8.x4.shared.b16 {%0,%1,%2,%3}, [%4];" \
        : "=r"((r)[0]), "=r"((r)[1]), "=r"((r)[2]), "=r"((r)[3]) : "r"(addr))

#define MMAF16(c, a, b0, b1) \
    asm volatile("mma.sync.aligned.m16n8k16.row.col.f32.f16.f16.f32 " \
        "{%0,%1,%2,%3}, {%4,%5,%6,%7}, {%8,%9}, {%0,%1,%2,%3};" \
        : "+f"((c)[0]), "+f"((c)[1]), "+f"((c)[2]), "+f"((c)[3]) \
        : "r"((a)[0]), "r"((a)[1]), "r"((a)[2]), "r"((a)[3]), "r"(b0), "r"(b1))

// ---------------- routing ----------------
__global__ void init_kernel() {
    int i = threadIdx.x;
    if (i < EE) { g_cnt1[i] = 0; g_cntA[i] = 0; g_psum[i] = 0.f; g_cur[i] = 0; }
}

__global__ void router_kernel(const float* __restrict__ x,
                              const float* __restrict__ rw) {
    __shared__ float s_psum[EE];
    __shared__ int s_cnt1[EE], s_cntA[EE];
    int tid = threadIdx.x;
    if (tid < EE) { s_psum[tid] = 0.f; s_cnt1[tid] = 0; s_cntA[tid] = 0; }
    __syncthreads();

    int warp = tid >> 5, lane = tid & 31;
    int t = blockIdx.x * 8 + warp;

    float acc[EE];
#pragma unroll
    for (int e = 0; e < EE; e++) acc[e] = 0.f;
    const float4* xr = reinterpret_cast<const float4*>(x + (long long)t * DD);
    for (int d4 = lane; d4 < DD / 4; d4 += 32) {
        float4 xv = xr[d4];
#pragma unroll
        for (int e = 0; e < EE; e++) {
            float4 wv = reinterpret_cast<const float4*>(rw + (long long)e * DD)[d4];
            acc[e] += xv.x * wv.x + xv.y * wv.y + xv.z * wv.z + xv.w * wv.w;
        }
    }
#pragma unroll
    for (int e = 0; e < EE; e++)
        for (int o = 16; o; o >>= 1)
            acc[e] += __shfl_xor_sync(0xffffffffu, acc[e], o);

    if (lane == 0) {
        float mx = acc[0];
#pragma unroll
        for (int e = 1; e < EE; e++) mx = fmaxf(mx, acc[e]);
        float p[EE], s = 0.f;
#pragma unroll
        for (int e = 0; e < EE; e++) { p[e] = expf(acc[e] - mx); s += p[e]; }
        float inv = 1.f / s;
        int e0 = 0;
#pragma unroll
        for (int e = 1; e < EE; e++) if (acc[e] > acc[e0]) e0 = e;
        int e1 = (e0 == 0) ? 1 : 0;
#pragma unroll
        for (int e = 0; e < EE; e++) if (e != e0 && acc[e] > acc[e1]) e1 = e;

        g_top_e[t] = make_int2(e0, e1);
        g_top_p[t] = make_float2(p[e0] * inv, p[e1] * inv);
        atomicAdd(&s_cnt1[e0], 1);
        atomicAdd(&s_cntA[e0], 1);
        atomicAdd(&s_cntA[e1], 1);
#pragma unroll
        for (int e = 0; e < EE; e++) atomicAdd(&s_psum[e], p[e] * inv);
    }
    __syncthreads();
    if (tid < EE) {
        atomicAdd(&g_psum[tid], s_psum[tid]);
        atomicAdd(&g_cnt1[tid], s_cnt1[tid]);
        atomicAdd(&g_cntA[tid], s_cntA[tid]);
    }
}

__global__ void scan_kernel(float* __restrict__ aux_out) {
    if (threadIdx.x == 0) {
        int off = 0;
        for (int e = 0; e < EE; e++) { g_seg[e] = off; off += g_cntA[e]; }
        g_seg[8] = TK;
        g_seg[9] = TKS;
        float aux = 0.f;
        const float invT = 1.0f / (float)TT;
        for (int e = 0; e < EE; e++)
            aux += ((float)g_cnt1[e] * invT) * (g_psum[e] * invT);
        aux_out[0] = 0.01f * (float)EE * aux;
    }
}

__global__ void build_kernel() {
    int t = blockIdx.x * blockDim.x + threadIdx.x;
    if (t >= TT) return;
    int2 e = g_top_e[t];
    float2 p = g_top_p[t];
    int pos0 = g_seg[e.x] + atomicAdd(&g_cur[e.x], 1);
    g_tok[pos0] = t; g_gatev[pos0] = p.x; g_pos[2 * t] = pos0;
    int pos1 = g_seg[e.y] + atomicAdd(&g_cur[e.y], 1);
    g_tok[pos1] = t; g_gatev[pos1] = p.y; g_pos[2 * t + 1] = pos1;
    g_tok[TK + t] = t; g_gatev[TK + t] = 1.0f;
}

// ---------------- gather + fp16 convert x ----------------
__global__ void gather_half_x(const float* __restrict__ x) {
    int i = blockIdx.x * blockDim.x + threadIdx.x;
    if (i >= TKS * (DD / 4)) return;
    int s = i >> 9;
    int c = i & 511;
    int tok = g_tok[s];
    float4 v = reinterpret_cast<const float4*>(x)[(long long)tok * (DD / 4) + c];
    __half2 lo = __floats2half2_rn(v.x, v.y);
    __half2 hi = __floats2half2_rn(v.z, v.w);
    long long o = (long long)s * (DD / 2) + c * 2;
    reinterpret_cast<__half2*>(g_xh)[o]     = lo;
    reinterpret_cast<__half2*>(g_xh)[o + 1] = hi;
}

// ---------------- fp16 convert weights ----------------
__global__ void conv_w(const float* __restrict__ src,
                       __half* __restrict__ dst, int n4) {
    int i = blockIdx.x * blockDim.x + threadIdx.x;
    if (i >= n4) return;
    float4 v = reinterpret_cast<const float4*>(src)[i];
    long long o = (long long)i * 2;
    reinterpret_cast<__half2*>(dst)[o]     = __floats2half2_rn(v.x, v.y);
    reinterpret_cast<__half2*>(dst)[o + 1] = __floats2half2_rn(v.z, v.w);
}

// ---------------- swiglu (fp32 in, fp16 out) ----------------
__global__ void swiglu_half(int n4) {
    int i = blockIdx.x * blockDim.x + threadIdx.x;
    if (i >= n4) return;
    float4 a = reinterpret_cast<const float4*>(g_bufA)[i];
    float4 b = reinterpret_cast<const float4*>(g_bufB)[i];
    float hx = a.x / (1.f + __expf(-a.x)) * b.x;
    float hy = a.y / (1.f + __expf(-a.y)) * b.y;
    float hz = a.z / (1.f + __expf(-a.z)) * b.z;
    float hw = a.w / (1.f + __expf(-a.w)) * b.w;
    long long o = (long long)i * 2;
    reinterpret_cast<__half2*>(g_hh)[o]     = __floats2half2_rn(hx, hy);
    reinterpret_cast<__half2*>(g_hh)[o + 1] = __floats2half2_rn(hz, hw);
}

// ============================================================================
// grouped FP16 GEMM via mma.sync m16n8k16 (single term, fp32 accumulate)
// C[m, col] = sum_k A[m,k] * W[z][n,k]
// 128x128 CTA tile, K32 chunks, 2-stage double buffer, 2 CTAs/SM.
// If W3 != null, blockIdx.x >= nxt selects the (W3, C3) pair (merged GEMM1).
// ============================================================================
#define MPITCH 80                           // bytes per smem row (conflict-stagger)
#define MTILE  (128 * MPITCH)               // 10240 bytes per operand tile
#define HSTAGE (2 * MTILE)                  // 20480 (A, B)
#define HSMEM  (2 * HSTAGE)                 // 40960 bytes total

__device__ __forceinline__ void ld_tiles_h(
    unsigned tb, int tid,
    const __half* __restrict__ A, const __half* __restrict__ B,
    int row0, int lda, int col0, int ldb, int nreal, int kreal, int kc0)
{
#pragma unroll
    for (int j = 0; j < 2; j++) {
        int idx = j * 256 + tid;         // 0..511
        int r = idx >> 2, c = idx & 3;   // tile row, 16B chunk (8 halves)
        unsigned off = (unsigned)(r * MPITCH + c * 16);
        int ar = row0 + r; if (ar >= TKS) ar = TKS - 1;
        long long ga = (long long)ar * lda + kc0 + c * 8;
        CP16(tb + off, A + ga, 16);
        int n = col0 + r, kg = kc0 + c * 8;
        int ok = (n < nreal && kg < kreal) ? 16 : 0;
        long long gb = ok ? ((long long)n * ldb + kg) : 0;
        CP16(tb + MTILE + off, B + gb, ok);
    }
    CP_COMMIT();
}

__global__ __launch_bounds__(256, 2)
void gemm_h(const __half* __restrict__ A,
            const __half* __restrict__ W1, const __half* __restrict__ W3,
            float* __restrict__ C1, float* __restrict__ C3,
            const float* __restrict__ gate,
            int lda, int ldb, int ldc, int nreal, int kreal, int kpad, int nxt)
{
    extern __shared__ __align__(128) char smem[];
    int z  = blockIdx.z;
    int m0 = g_seg[z], m1 = g_seg[z + 1];
    int row0 = m0 + blockIdx.y * 128;
    if (row0 >= m1) return;

    const __half* W = W1;
    float* C = C1;
    int cx = blockIdx.x;
    if (W3 != nullptr && cx >= nxt) { W = W3; C = C3; cx -= nxt; }
    int col0 = cx * 128;

    const __half* B = W + (long long)z * WMAT;

    unsigned sb = smem_u32(smem);
    int tid = threadIdx.x, wid = tid >> 5, lane = tid & 31;
    int nch = kpad / 32;
    int wm = wid & 3, wn = wid >> 2;          // warp -> (m32 slot, n64 slot)

    float acc[2][8][4];
#pragma unroll
    for (int t = 0; t < 2; t++)
#pragma unroll
        for (int n = 0; n < 8; n++)
#pragma unroll
            for (int q = 0; q < 4; q++) acc[t][n][q] = 0.f;

    // ldmatrix lane offsets (f16 family; k-step byte advance added in loop)
    unsigned a_off[2], b_off[4];
#pragma unroll
    for (int t = 0; t < 2; t++) {
        int rr = wm * 32 + t * 16 + ((lane >> 3) & 1) * 8 + (lane & 7);
        a_off[t] = (unsigned)(rr * MPITCH + (lane >> 4) * 16);
    }
#pragma unroll
    for (int p = 0; p < 4; p++) {
        int nn = wn * 64 + p * 16 + (lane >> 4) * 8 + (lane & 7);
        b_off[p] = (unsigned)(nn * MPITCH + ((lane >> 3) & 1) * 16);
    }

    ld_tiles_h(sb, tid, A, B, row0, lda, col0, ldb, nreal, kreal, 0);

    for (int i = 0; i < nch; i++) {
        if (i + 1 < nch) {
            ld_tiles_h(sb + ((i + 1) & 1) * HSTAGE, tid, A, B,
                       row0, lda, col0, ldb, nreal, kreal, (i + 1) * 32);
            CP_WAIT1();
        } else {
            CP_WAIT0();
        }
        __syncthreads();

        unsigned tb = sb + (i & 1) * HSTAGE;
#pragma unroll
        for (int ks = 0; ks < 2; ks++) {
            unsigned kof = ks * 32;          // 16 halves = 32 bytes per k16 step
            unsigned av[2][4], bv[4][4];
            LDSM4(av[0], tb + a_off[0] + kof);
            LDSM4(av[1], tb + a_off[1] + kof);
#pragma unroll
            for (int p = 0; p < 4; p++)
                LDSM4(bv[p], tb + MTILE + b_off[p] + kof);
#pragma unroll
            for (int p = 0; p < 4; p++)
#pragma unroll
                for (int t = 0; t < 2; t++) {
                    MMAF16(acc[t][2 * p],     av[t], bv[p][0], bv[p][1]);
                    MMAF16(acc[t][2 * p + 1], av[t], bv[p][2], bv[p][3]);
                }
        }
        __syncthreads();
    }

    // epilogue
#pragma unroll
    for (int t = 0; t < 2; t++) {
        int r0 = row0 + wm * 32 + t * 16 + (lane >> 2);
        int r1 = r0 + 8;
        float g0 = 1.f, g1 = 1.f;
        bool a0 = (r0 < m1), a1 = (r1 < m1);
        if (gate != nullptr) {
            if (a0) g0 = gate[r0];
            if (a1) g1 = gate[r1];
        }
#pragma unroll
        for (int n = 0; n < 8; n++) {
            int cb = col0 + wn * 64 + n * 8 + 2 * (lane & 3);
            if (a0) {
                float2 v = make_float2(acc[t][n][0] * g0, acc[t][n][1] * g0);
                *reinterpret_cast<float2*>(C + (long long)r0 * ldc + cb) = v;
            }
            if (a1) {
                float2 v = make_float2(acc[t][n][2] * g1, acc[t][n][3] * g1);
                *reinterpret_cast<float2*>(C + (long long)r1 * ldc + cb) = v;
            }
        }
    }
}

// ---------------- final deterministic 3-slot add ----------------
__global__ void final_add(float* __restrict__ out) {
    int i = blockIdx.x * blockDim.x + threadIdx.x;
    if (i >= TT * (DD / 4)) return;
    int t = i >> 9, c = i & 511;
    int p0 = g_pos[2 * t], p1 = g_pos[2 * t + 1], p2 = TK + t;
    const float4* y4 = reinterpret_cast<const float4*>(g_y);
    float4 a = y4[(long long)p0 * 512 + c];
    float4 b = y4[(long long)p1 * 512 + c];
    float4 d = y4[(long long)p2 * 512 + c];
    float4 v;
    v.x = a.x + b.x + d.x; v.y = a.y + b.y + d.y;
    v.z = a.z + b.z + d.z; v.w = a.w + b.w + d.w;
    reinterpret_cast<float4*>(out)[(long long)t * 512 + c] = v;
}

// ---------------- launch ----------------
extern "C" void kernel_launch(void* const* d_in, const int* in_sizes, int n_in,
                              void* d_out, int out_size) {
    const float* x   = (const float*)d_in[0];
    const float* rw  = (const float*)d_in[1];
    const float* w1  = (const float*)d_in[2];
    const float* w2  = (const float*)d_in[3];
    const float* w3  = (const float*)d_in[4];
    const float* sw1 = (const float*)d_in[5];
    const float* sw2 = (const float*)d_in[6];
    const float* sw3 = (const float*)d_in[7];
    float* out = (float*)d_out;

    float *pBufA, *pBufB, *pY, *pGate;
    __half *pXh, *pHh, *pW1h, *pW3h, *pW2h;
    cudaGetSymbolAddress((void**)&pBufA, g_bufA);
    cudaGetSymbolAddress((void**)&pBufB, g_bufB);
    cudaGetSymbolAddress((void**)&pY,    g_y);
    cudaGetSymbolAddress((void**)&pGate, g_gatev);
    cudaGetSymbolAddress((void**)&pXh,   g_xh);
    cudaGetSymbolAddress((void**)&pHh,   g_hh);
    cudaGetSymbolAddress((void**)&pW1h,  g_w1h);
    cudaGetSymbolAddress((void**)&pW3h,  g_w3h);
    cudaGetSymbolAddress((void**)&pW2h,  g_w2h);

    cudaFuncSetAttribute(gemm_h, cudaFuncAttributeMaxDynamicSharedMemorySize, HSMEM);

    // routing
    init_kernel<<<1, 32>>>();
    router_kernel<<<TT / 8, 256>>>(x, rw);
    scan_kernel<<<1, 32>>>(out + (long long)TT * DD);
    build_kernel<<<TT / 256, 256>>>();

    // gather + converts
    gather_half_x<<<(TKS * (DD / 4) + 255) / 256, 256>>>(x);
    int nw = 8 * WMAT / 4, ns = WMAT / 4;
    conv_w<<<(nw + 255) / 256, 256>>>(w1,  pW1h,                    nw);
    conv_w<<<(ns + 255) / 256, 256>>>(sw1, pW1h + (size_t)8 * WMAT, ns);
    conv_w<<<(nw + 255) / 256, 256>>>(w3,  pW3h,                    nw);
    conv_w<<<(ns + 255) / 256, 256>>>(sw3, pW3h + (size_t)8 * WMAT, ns);
    conv_w<<<(nw + 255) / 256, 256>>>(w2,  pW2h,                    nw);
    conv_w<<<(ns + 255) / 256, 256>>>(sw2, pW2h + (size_t)8 * WMAT, ns);

    // GEMM1 merged: grid.x < 11 -> w1 -> bufA; >= 11 -> w3 -> bufB
    dim3 grid1(22, 64, 9);
    gemm_h<<<grid1, 256, HSMEM>>>(pXh, pW1h, pW3h, pBufA, pBufB, nullptr,
                                  DD, DD, HP, HH, DD, DD, 11);

    // swiglu -> fp16
    {
        int n4 = TKS * HP / 4;
        swiglu_half<<<(n4 + 255) / 256, 256>>>(n4);
    }

    // GEMM2: [TKS, HP] @ [DD, HH]^T -> y (gated); K iterates 1376 (>= HH)
    dim3 grid2(16, 64, 9);
    gemm_h<<<grid2, 256, HSMEM>>>(pHh, pW2h, nullptr, pY, nullptr, pGate,
                                  HP, HH, DD, DD, HH, 1376, 16);

    final_add<<<(TT * (DD / 4)) / 256, 256>>>(out);
}

// round 10
// speedup vs baseline: 2.6461x; 1.1396x over previous
#include <cuda_runtime.h>
#include <cuda_fp16.h>
#include <math.h>
#include <stdint.h>

// ---------------- problem constants ----------------
#define TT   8192              // tokens (B*S)
#define DD   2048              // model dim
#define HH   1368              // hidden dim
#define HP   1408              // hidden padded to 64
#define EE   8                 // experts
#define TK   16384             // T * K routed assignments
#define TKS  24576             // TK + TT (shared expert appended as segment 8)
#define WMAT (HH * DD)         // elements per weight matrix

// ---------------- static device scratch ----------------
__device__ __align__(16) __half g_xh[(size_t)TKS * DD];    // gathered x (fp16)
__device__ __align__(16) __half g_hh[(size_t)TKS * HP];    // swiglu output (fp16)
__device__ __align__(16) float  g_bufA[(size_t)TKS * HP];  // x@w1^T (fp32)
__device__ __align__(16) float  g_bufB[(size_t)TKS * HP];  // x@w3^T (fp32)
__device__ __align__(16) float  g_y[(size_t)TKS * DD];     // gemm2 output slots
__device__ __align__(16) __half g_w1h[(size_t)9 * WMAT];
__device__ __align__(16) __half g_w3h[(size_t)9 * WMAT];
__device__ __align__(16) __half g_w2h[(size_t)9 * WMAT];
__device__ int    g_tok[TKS];
__device__ float  g_gatev[TKS];
__device__ int    g_pos[2 * TT];
__device__ int2   g_top_e[TT];
__device__ float2 g_top_p[TT];
__device__ int    g_cnt1[EE];
__device__ int    g_cntA[EE];
__device__ int    g_cur[EE];
__device__ int    g_seg[10];
__device__ float  g_psum[EE];

// ---------------- PTX helpers (baseline-arch safe) ----------------
__device__ __forceinline__ unsigned smem_u32(const void* p) {
    unsigned a;
    asm("{ .reg .u64 t; cvta.to.shared.u64 t, %1; cvt.u32.u64 %0, t; }"
        : "=r"(a) : "l"(p));
    return a;
}
#define CP_COMMIT()  asm volatile("cp.async.commit_group;" ::: "memory")
#define CP_WAIT0()   asm volatile("cp.async.wait_group 0;" ::: "memory")
#define CP_WAIT1()   asm volatile("cp.async.wait_group 1;" ::: "memory")
#define CP16(dst, src, sz) \
    asm volatile("cp.async.cg.shared.global [%0], [%1], 16, %2;" \
                 :: "r"(dst), "l"(src), "r"(sz))

#define LDSM4(r, addr) \
    asm volatile("ldmatrix.sync.aligned.m8n8.x4.shared.b16 {%0,%1,%2,%3}, [%4];" \
        : "=r"((r)[0]), "=r"((r)[1]), "=r"((r)[2]), "=r"((r)[3]) : "r"(addr))

#define MMAF16(c, a, b0, b1) \
    asm volatile("mma.sync.aligned.m16n8k16.row.col.f32.f16.f16.f32 " \
        "{%0,%1,%2,%3}, {%4,%5,%6,%7}, {%8,%9}, {%0,%1,%2,%3};" \
        : "+f"((c)[0]), "+f"((c)[1]), "+f"((c)[2]), "+f"((c)[3]) \
        : "r"((a)[0]), "r"((a)[1]), "r"((a)[2]), "r"((a)[3]), "r"(b0), "r"(b1))

// ---------------- routing ----------------
__global__ void init_kernel() {
    int i = threadIdx.x;
    if (i < EE) { g_cnt1[i] = 0; g_cntA[i] = 0; g_psum[i] = 0.f; g_cur[i] = 0; }
}

__global__ void router_kernel(const float* __restrict__ x,
                              const float* __restrict__ rw) {
    __shared__ float s_psum[EE];
    __shared__ int s_cnt1[EE], s_cntA[EE];
    int tid = threadIdx.x;
    if (tid < EE) { s_psum[tid] = 0.f; s_cnt1[tid] = 0; s_cntA[tid] = 0; }
    __syncthreads();

    int warp = tid >> 5, lane = tid & 31;
    int t = blockIdx.x * 8 + warp;

    float acc[EE];
#pragma unroll
    for (int e = 0; e < EE; e++) acc[e] = 0.f;
    const float4* xr = reinterpret_cast<const float4*>(x + (long long)t * DD);
    for (int d4 = lane; d4 < DD / 4; d4 += 32) {
        float4 xv = xr[d4];
#pragma unroll
        for (int e = 0; e < EE; e++) {
            float4 wv = reinterpret_cast<const float4*>(rw + (long long)e * DD)[d4];
            acc[e] += xv.x * wv.x + xv.y * wv.y + xv.z * wv.z + xv.w * wv.w;
        }
    }
#pragma unroll
    for (int e = 0; e < EE; e++)
        for (int o = 16; o; o >>= 1)
            acc[e] += __shfl_xor_sync(0xffffffffu, acc[e], o);

    if (lane == 0) {
        float mx = acc[0];
#pragma unroll
        for (int e = 1; e < EE; e++) mx = fmaxf(mx, acc[e]);
        float p[EE], s = 0.f;
#pragma unroll
        for (int e = 0; e < EE; e++) { p[e] = expf(acc[e] - mx); s += p[e]; }
        float inv = 1.f / s;
        int e0 = 0;
#pragma unroll
        for (int e = 1; e < EE; e++) if (acc[e] > acc[e0]) e0 = e;
        int e1 = (e0 == 0) ? 1 : 0;
#pragma unroll
        for (int e = 0; e < EE; e++) if (e != e0 && acc[e] > acc[e1]) e1 = e;

        g_top_e[t] = make_int2(e0, e1);
        g_top_p[t] = make_float2(p[e0] * inv, p[e1] * inv);
        atomicAdd(&s_cnt1[e0], 1);
        atomicAdd(&s_cntA[e0], 1);
        atomicAdd(&s_cntA[e1], 1);
#pragma unroll
        for (int e = 0; e < EE; e++) atomicAdd(&s_psum[e], p[e] * inv);
    }
    __syncthreads();
    if (tid < EE) {
        atomicAdd(&g_psum[tid], s_psum[tid]);
        atomicAdd(&g_cnt1[tid], s_cnt1[tid]);
        atomicAdd(&g_cntA[tid], s_cntA[tid]);
    }
}

__global__ void scan_kernel(float* __restrict__ aux_out) {
    if (threadIdx.x == 0) {
        int off = 0;
        for (int e = 0; e < EE; e++) { g_seg[e] = off; off += g_cntA[e]; }
        g_seg[8] = TK;
        g_seg[9] = TKS;
        float aux = 0.f;
        const float invT = 1.0f / (float)TT;
        for (int e = 0; e < EE; e++)
            aux += ((float)g_cnt1[e] * invT) * (g_psum[e] * invT);
        aux_out[0] = 0.01f * (float)EE * aux;
    }
}

__global__ void build_kernel() {
    int t = blockIdx.x * blockDim.x + threadIdx.x;
    if (t >= TT) return;
    int2 e = g_top_e[t];
    float2 p = g_top_p[t];
    int pos0 = g_seg[e.x] + atomicAdd(&g_cur[e.x], 1);
    g_tok[pos0] = t; g_gatev[pos0] = p.x; g_pos[2 * t] = pos0;
    int pos1 = g_seg[e.y] + atomicAdd(&g_cur[e.y], 1);
    g_tok[pos1] = t; g_gatev[pos1] = p.y; g_pos[2 * t + 1] = pos1;
    g_tok[TK + t] = t; g_gatev[TK + t] = 1.0f;
}

// ---------------- gather + fp16 convert x ----------------
__global__ void gather_half_x(const float* __restrict__ x) {
    int i = blockIdx.x * blockDim.x + threadIdx.x;
    if (i >= TKS * (DD / 4)) return;
    int s = i >> 9;
    int c = i & 511;
    int tok = g_tok[s];
    float4 v = reinterpret_cast<const float4*>(x)[(long long)tok * (DD / 4) + c];
    long long o = (long long)s * (DD / 2) + c * 2;
    reinterpret_cast<__half2*>(g_xh)[o]     = __floats2half2_rn(v.x, v.y);
    reinterpret_cast<__half2*>(g_xh)[o + 1] = __floats2half2_rn(v.z, v.w);
}

// ---------------- fp16 convert weights ----------------
__global__ void conv_w(const float* __restrict__ src,
                       __half* __restrict__ dst, int n4) {
    int i = blockIdx.x * blockDim.x + threadIdx.x;
    if (i >= n4) return;
    float4 v = reinterpret_cast<const float4*>(src)[i];
    long long o = (long long)i * 2;
    reinterpret_cast<__half2*>(dst)[o]     = __floats2half2_rn(v.x, v.y);
    reinterpret_cast<__half2*>(dst)[o + 1] = __floats2half2_rn(v.z, v.w);
}

// ---------------- swiglu (fp32 in, fp16 out) ----------------
__global__ void swiglu_half(int n4) {
    int i = blockIdx.x * blockDim.x + threadIdx.x;
    if (i >= n4) return;
    float4 a = reinterpret_cast<const float4*>(g_bufA)[i];
    float4 b = reinterpret_cast<const float4*>(g_bufB)[i];
    float hx = a.x / (1.f + __expf(-a.x)) * b.x;
    float hy = a.y / (1.f + __expf(-a.y)) * b.y;
    float hz = a.z / (1.f + __expf(-a.z)) * b.z;
    float hw = a.w / (1.f + __expf(-a.w)) * b.w;
    long long o = (long long)i * 2;
    reinterpret_cast<__half2*>(g_hh)[o]     = __floats2half2_rn(hx, hy);
    reinterpret_cast<__half2*>(g_hh)[o + 1] = __floats2half2_rn(hz, hw);
}

// ============================================================================
// grouped FP16 GEMM via mma.sync m16n8k16 (fp32 accumulate)
// C[m, col] = sum_k A[m,k] * W[z][n,k]
// 128x128 CTA tile, K64 chunks, 2-stage double buffer, 2 CTAs/SM.
// If W3 != null, blockIdx.x >= nxt selects the (W3, C3) pair (merged GEMM1).
// ============================================================================
#define MPITCH 144                          // 128B K64 data + 16B stagger
#define MTILE  (128 * MPITCH)               // 18432 bytes per operand tile
#define HSTAGE (2 * MTILE)                  // 36864 (A, B)
#define HSMEM  (2 * HSTAGE)                 // 73728 bytes total

__device__ __forceinline__ void ld_tiles_h(
    unsigned tb, int tid,
    const __half* __restrict__ A, const __half* __restrict__ B,
    int row0, int lda, int col0, int ldb, int nreal, int kreal, int kc0)
{
#pragma unroll
    for (int j = 0; j < 8; j++) {
        int idx = j * 256 + tid;         // 0..2047
        int li = idx & 1023;
        int r = li >> 3, c = li & 7;     // tile row, 16B k-chunk (8 halves)
        unsigned off = (unsigned)(r * MPITCH + c * 16);
        if (idx < 1024) {
            int ar = row0 + r; if (ar >= TKS) ar = TKS - 1;
            long long ga = (long long)ar * lda + kc0 + c * 8;
            CP16(tb + off, A + ga, 16);
        } else {
            int n = col0 + r, kg = kc0 + c * 8;
            int ok = (n < nreal && kg < kreal) ? 16 : 0;
            long long gb = ok ? ((long long)n * ldb + kg) : 0;
            CP16(tb + MTILE + off, B + gb, ok);
        }
    }
    CP_COMMIT();
}

__global__ __launch_bounds__(256, 2)
void gemm_h(const __half* __restrict__ A,
            const __half* __restrict__ W1, const __half* __restrict__ W3,
            float* __restrict__ C1, float* __restrict__ C3,
            const float* __restrict__ gate,
            int lda, int ldb, int ldc, int nreal, int kreal, int kpad, int nxt)
{
    extern __shared__ __align__(128) char smem[];
    int z  = blockIdx.z;
    int m0 = g_seg[z], m1 = g_seg[z + 1];
    int row0 = m0 + blockIdx.y * 128;
    if (row0 >= m1) return;

    const __half* W = W1;
    float* C = C1;
    int cx = blockIdx.x;
    if (W3 != nullptr && cx >= nxt) { W = W3; C = C3; cx -= nxt; }
    int col0 = cx * 128;

    const __half* B = W + (long long)z * WMAT;

    unsigned sb = smem_u32(smem);
    int tid = threadIdx.x, wid = tid >> 5, lane = tid & 31;
    int nch = kpad / 64;
    int wm = wid & 3, wn = wid >> 2;          // warp -> (m32 slot, n64 slot)

    float acc[2][8][4];
#pragma unroll
    for (int t = 0; t < 2; t++)
#pragma unroll
        for (int n = 0; n < 8; n++)
#pragma unroll
            for (int q = 0; q < 4; q++) acc[t][n][q] = 0.f;

    // ldmatrix lane offsets (f16 family; k-step byte advance added in loop)
    unsigned a_off[2], b_off[4];
#pragma unroll
    for (int t = 0; t < 2; t++) {
        int rr = wm * 32 + t * 16 + ((lane >> 3) & 1) * 8 + (lane & 7);
        a_off[t] = (unsigned)(rr * MPITCH + (lane >> 4) * 16);
    }
#pragma unroll
    for (int p = 0; p < 4; p++) {
        int nn = wn * 64 + p * 16 + (lane >> 4) * 8 + (lane & 7);
        b_off[p] = (unsigned)(nn * MPITCH + ((lane >> 3) & 1) * 16);
    }

    ld_tiles_h(sb, tid, A, B, row0, lda, col0, ldb, nreal, kreal, 0);

    for (int i = 0; i < nch; i++) {
        if (i + 1 < nch) {
            ld_tiles_h(sb + ((i + 1) & 1) * HSTAGE, tid, A, B,
                       row0, lda, col0, ldb, nreal, kreal, (i + 1) * 64);
            CP_WAIT1();
        } else {
            CP_WAIT0();
        }
        __syncthreads();

        unsigned tb = sb + (i & 1) * HSTAGE;
#pragma unroll
        for (int ks = 0; ks < 4; ks++) {
            unsigned kof = ks * 32;          // 16 halves = 32 bytes per k16 step
            unsigned av[2][4], bv[4][4];
            LDSM4(av[0], tb + a_off[0] + kof);
            LDSM4(av[1], tb + a_off[1] + kof);
#pragma unroll
            for (int p = 0; p < 4; p++)
                LDSM4(bv[p], tb + MTILE + b_off[p] + kof);
#pragma unroll
            for (int p = 0; p < 4; p++)
#pragma unroll
                for (int t = 0; t < 2; t++) {
                    MMAF16(acc[t][2 * p],     av[t], bv[p][0], bv[p][1]);
                    MMAF16(acc[t][2 * p + 1], av[t], bv[p][2], bv[p][3]);
                }
        }
        __syncthreads();
    }

    // epilogue
#pragma unroll
    for (int t = 0; t < 2; t++) {
        int r0 = row0 + wm * 32 + t * 16 + (lane >> 2);
        int r1 = r0 + 8;
        float g0 = 1.f, g1 = 1.f;
        bool a0 = (r0 < m1), a1 = (r1 < m1);
        if (gate != nullptr) {
            if (a0) g0 = gate[r0];
            if (a1) g1 = gate[r1];
        }
#pragma unroll
        for (int n = 0; n < 8; n++) {
            int cb = col0 + wn * 64 + n * 8 + 2 * (lane & 3);
            if (a0) {
                float2 v = make_float2(acc[t][n][0] * g0, acc[t][n][1] * g0);
                *reinterpret_cast<float2*>(C + (long long)r0 * ldc + cb) = v;
            }
            if (a1) {
                float2 v = make_float2(acc[t][n][2] * g1, acc[t][n][3] * g1);
                *reinterpret_cast<float2*>(C + (long long)r1 * ldc + cb) = v;
            }
        }
    }
}

// ---------------- final deterministic 3-slot add ----------------
__global__ void final_add(float* __restrict__ out) {
    int i = blockIdx.x * blockDim.x + threadIdx.x;
    if (i >= TT * (DD / 4)) return;
    int t = i >> 9, c = i & 511;
    int p0 = g_pos[2 * t], p1 = g_pos[2 * t + 1], p2 = TK + t;
    const float4* y4 = reinterpret_cast<const float4*>(g_y);
    float4 a = y4[(long long)p0 * 512 + c];
    float4 b = y4[(long long)p1 * 512 + c];
    float4 d = y4[(long long)p2 * 512 + c];
    float4 v;
    v.x = a.x + b.x + d.x; v.y = a.y + b.y + d.y;
    v.z = a.z + b.z + d.z; v.w = a.w + b.w + d.w;
    reinterpret_cast<float4*>(out)[(long long)t * 512 + c] = v;
}

// ---------------- launch ----------------
extern "C" void kernel_launch(void* const* d_in, const int* in_sizes, int n_in,
                              void* d_out, int out_size) {
    const float* x   = (const float*)d_in[0];
    const float* rw  = (const float*)d_in[1];
    const float* w1  = (const float*)d_in[2];
    const float* w2  = (const float*)d_in[3];
    const float* w3  = (const float*)d_in[4];
    const float* sw1 = (const float*)d_in[5];
    const float* sw2 = (const float*)d_in[6];
    const float* sw3 = (const float*)d_in[7];
    float* out = (float*)d_out;

    float *pBufA, *pBufB, *pY, *pGate;
    __half *pXh, *pHh, *pW1h, *pW3h, *pW2h;
    cudaGetSymbolAddress((void**)&pBufA, g_bufA);
    cudaGetSymbolAddress((void**)&pBufB, g_bufB);
    cudaGetSymbolAddress((void**)&pY,    g_y);
    cudaGetSymbolAddress((void**)&pGate, g_gatev);
    cudaGetSymbolAddress((void**)&pXh,   g_xh);
    cudaGetSymbolAddress((void**)&pHh,   g_hh);
    cudaGetSymbolAddress((void**)&pW1h,  g_w1h);
    cudaGetSymbolAddress((void**)&pW3h,  g_w3h);
    cudaGetSymbolAddress((void**)&pW2h,  g_w2h);

    cudaFuncSetAttribute(gemm_h, cudaFuncAttributeMaxDynamicSharedMemorySize, HSMEM);

    // routing
    init_kernel<<<1, 32>>>();
    router_kernel<<<TT / 8, 256>>>(x, rw);
    scan_kernel<<<1, 32>>>(out + (long long)TT * DD);
    build_kernel<<<TT / 256, 256>>>();

    // gather + converts
    gather_half_x<<<(TKS * (DD / 4) + 255) / 256, 256>>>(x);
    int nw = 8 * WMAT / 4, ns = WMAT / 4;
    conv_w<<<(nw + 255) / 256, 256>>>(w1,  pW1h,                    nw);
    conv_w<<<(ns + 255) / 256, 256>>>(sw1, pW1h + (size_t)8 * WMAT, ns);
    conv_w<<<(nw + 255) / 256, 256>>>(w3,  pW3h,                    nw);
    conv_w<<<(ns + 255) / 256, 256>>>(sw3, pW3h + (size_t)8 * WMAT, ns);
    conv_w<<<(nw + 255) / 256, 256>>>(w2,  pW2h,                    nw);
    conv_w<<<(ns + 255) / 256, 256>>>(sw2, pW2h + (size_t)8 * WMAT, ns);

    // GEMM1 merged: grid.x < 11 -> w1 -> bufA; >= 11 -> w3 -> bufB
    dim3 grid1(22, 64, 9);
    gemm_h<<<grid1, 256, HSMEM>>>(pXh, pW1h, pW3h, pBufA, pBufB, nullptr,
                                  DD, DD, HP, HH, DD, 2048, 11);

    // swiglu -> fp16
    {
        int n4 = TKS * HP / 4;
        swiglu_half<<<(n4 + 255) / 256, 256>>>(n4);
    }

    // GEMM2: [TKS, HP] @ [DD, HH]^T -> y (gated); kpad 1408, guards at k>=1368
    dim3 grid2(16, 64, 9);
    gemm_h<<<grid2, 256, HSMEM>>>(pHh, pW2h, nullptr, pY, nullptr, pGate,
                                  HP, HH, DD, DD, HH, 1408, 16);

    final_add<<<(TT * (DD / 4)) / 256, 256>>>(out);
}